// round 16
// baseline (speedup 1.0000x reference)
#include <cuda_runtime.h>
#include <cuda_fp16.h>
#include <math.h>
#include <cfloat>
#include <stdint.h>

#define Bv 8
#define Sv 256
#define Ev 256
#define Hv 8
#define ROWS (Bv*Sv)

__device__ float g_cnnp[(size_t)2*ROWS*Ev];   // partial maxes per l-half
__device__ float g_feat[ROWS*Ev];
__device__ float g_h[ROWS*Ev];
__device__ float g_hn[ROWS*Ev];
__device__ float g_q[ROWS*Ev];
__device__ float g_k[ROWS*Ev];
__device__ float g_v[ROWS*Ev];
__device__ float g_attno[ROWS*Ev];
__device__ float g_ffn[ROWS*2*Ev];
__device__ float g_dist[Bv*Sv*Sv];
__device__ float g_sq[ROWS];
__device__ float g_pooled[Bv*8*Ev];
__device__ unsigned g_dmax;
__device__ uint32_t g_h1q[(size_t)2048*64*264];     // [sb][c2][l padded 264] half2
__device__ uint32_t g_w2p[(size_t)256*192*256];     // [s][k2=ks*64+c2][e] half2

__device__ __forceinline__ float warpSum(float v){
    #pragma unroll
    for(int o=16;o>0;o>>=1) v += __shfl_xor_sync(0xFFFFFFFFu,v,o);
    return v;
}
__device__ __forceinline__ float warpMax(float v){
    #pragma unroll
    for(int o=16;o>0;o>>=1) v = fmaxf(v,__shfl_xor_sync(0xFFFFFFFFu,v,o));
    return v;
}
__device__ __forceinline__ void cpa16(void* sm, const void* g){
    unsigned sa = (unsigned)__cvta_generic_to_shared(sm);
    asm volatile("cp.async.cg.shared.global [%0], [%1], 16;" :: "r"(sa), "l"(g));
}
#define CP_COMMIT() asm volatile("cp.async.commit_group;")
#define CP_WAIT(N)  asm volatile("cp.async.wait_group %0;" :: "n"(N))
#define MMA_F16(C,A,B) \
    asm volatile("mma.sync.aligned.m16n8k16.row.col.f32.f16.f16.f32 " \
        "{%0,%1,%2,%3},{%4,%5,%6,%7},{%8,%9},{%0,%1,%2,%3};" \
        : "+f"((C)[0]),"+f"((C)[1]),"+f"((C)[2]),"+f"((C)[3]) \
        : "r"((A)[0]),"r"((A)[1]),"r"((A)[2]),"r"((A)[3]),"r"((B)[0]),"r"((B)[1]))

__device__ __forceinline__ uint32_t h2pack(float a, float b){
    __half2 h = __floats2half2_rn(a,b);
    return *(uint32_t*)&h;
}

__global__ void init_kernel(){ if(threadIdx.x==0) g_dmax=0u; }

// ---- conv1 -> g_h1q packed half2 [sb][c2][264], zero pads at l=0, 257..263 ----
__global__ __launch_bounds__(256) void conv1_kernel(
    const float* __restrict__ x, const float* __restrict__ w1, const float* __restrict__ b1)
{
    __shared__ float xs[4*258], w1s[1536], b1s[128];
    int t=threadIdx.x, sb=blockIdx.x, s=sb>>3, b=sb&7;
    for(int idx=t; idx<4*258; idx+=256){
        int ci=idx/258, p=idx-ci*258; float v=0.f;
        if(p>=1 && p<=256) v = x[((b*Sv+s)*4+ci)*256 + p-1];
        xs[idx]=v;
    }
    for(int idx=t; idx<1536; idx+=256) w1s[idx]=w1[s*1536+idx];
    if(t<128) b1s[t]=b1[s*128+t];
    __syncthreads();
    for(int idx=t; idx<64*256; idx+=256){
        int c2=idx>>8, l=idx&255;
        float a0=b1s[2*c2], a1=b1s[2*c2+1];
        const float* w0=&w1s[(2*c2)*12];
        const float* w1r=&w1s[(2*c2+1)*12];
        #pragma unroll
        for(int ci=0;ci<4;ci++){
            const float* xr=&xs[ci*258+l];
            a0=fmaf(xr[0],w0[ci*3+0],a0); a0=fmaf(xr[1],w0[ci*3+1],a0); a0=fmaf(xr[2],w0[ci*3+2],a0);
            a1=fmaf(xr[0],w1r[ci*3+0],a1); a1=fmaf(xr[1],w1r[ci*3+1],a1); a1=fmaf(xr[2],w1r[ci*3+2],a1);
        }
        g_h1q[((size_t)sb*64 + c2)*264 + l + 1] = h2pack(fmaxf(a0,0.f), fmaxf(a1,0.f));
    }
    for(int idx=t; idx<64*8; idx+=256){
        int c2=idx>>3, q=idx&7, p=(q==0)?0:(256+q);
        g_h1q[((size_t)sb*64+c2)*264 + p]=0u;
    }
}

// ---- w2 -> g_w2p packed half2 [s][k2=ks*64+c2][e] ----
__global__ __launch_bounds__(256) void w2p_kernel(const float* __restrict__ w2)
{
    int t=threadIdx.x, bx=blockIdx.x;
    int s=bx>>3, part=bx&7;
    for(int i=t;i<6144;i+=256){
        int j = part*6144 + i;
        int k2 = j>>8, e = j&255;
        int ks = k2>>6, c2 = k2&63;
        const float* src = w2 + ((size_t)(s*256+e))*384;
        g_w2p[((size_t)s*192 + k2)*256 + e] = h2pack(src[(2*c2)*3+ks], src[(2*c2+1)*3+ks]);
    }
}

// ---- conv2 fp16 MMA GEMM, tile 64e x 128l, occupancy-2, single-buffered ----
#define C2_ASW 72
#define C2_BSW 136
#define C2_AW  (96*C2_ASW)            // 6912
#define C2_ST  (C2_AW + 32*C2_BSW)    // 11264 words = 45056 B
#define CONV2_SMEM_BYTES (C2_ST*4)

__global__ __launch_bounds__(256,2) void conv2_mma_kernel()
{
    extern __shared__ float smcf[];
    uint32_t* smc = (uint32_t*)smcf;
    int t=threadIdx.x, bx=blockIdx.x;
    int s=bx>>6, eq=(bx>>4)&3, b=(bx>>1)&7, lh=bx&1, sb=s*8+b;
    int lane=t&31, wid=t>>5, gg=lane>>2, tg=lane&3;
    int wm=wid&1, wn=wid>>1;
    int e0=eq*64;
    const uint32_t* Ag = g_w2p + (size_t)s*192*256 + e0;
    const uint32_t* Bg = g_h1q + (size_t)sb*64*264 + lh*128;

    float acc[2][4][4];
    #pragma unroll
    for(int i=0;i<2;i++)
        #pragma unroll
        for(int j=0;j<4;j++)
            #pragma unroll
            for(int q=0;q<4;q++) acc[i][j][q]=0.f;

    uint32_t* As = smc;
    uint32_t* Bs = smc + C2_AW;

    #pragma unroll
    for(int cc=0; cc<2; cc++){
        if(cc) __syncthreads();   // protect buffer reuse
        // A: 96 rows (3ks x 32 c2) x 64 e
        #pragma unroll
        for(int i=0;i<6;i++){
            int idx=t+i*256, ks=idx>>9, rem=idx&511, rr=rem>>4, f=rem&15;
            cpa16(As+(ks*32+rr)*C2_ASW+f*4,
                  Ag+((size_t)(ks*64+cc*32+rr))*256+f*4);
        }
        // B: 32 c2 rows x 136 l-words (covers l-half + tap halo)
        #pragma unroll
        for(int i=0;i<5;i++){
            int idx=t+i*256;
            if(idx<1088){
                int r=idx/34, f=idx-r*34;
                cpa16(Bs+r*C2_BSW+f*4, Bg+((size_t)(cc*32+r))*264+f*4);
            }
        }
        CP_COMMIT(); CP_WAIT(0);
        __syncthreads();
        #pragma unroll
        for(int ks=0; ks<3; ks++){
            #pragma unroll
            for(int kk=0; kk<4; kk++){
                int kr = ks*32 + kk*8 + tg;
                int kb = kk*8 + tg;
                uint32_t af[2][4];
                #pragma unroll
                for(int mi=0;mi<2;mi++){
                    int e = wm*32 + mi*16 + gg;
                    af[mi][0]=As[kr*C2_ASW+e];     af[mi][1]=As[kr*C2_ASW+e+8];
                    af[mi][2]=As[(kr+4)*C2_ASW+e]; af[mi][3]=As[(kr+4)*C2_ASW+e+8];
                }
                uint32_t bf[4][2];
                #pragma unroll
                for(int nj=0;nj<4;nj++){
                    int n = ks + wn*32 + nj*8 + gg;   // +ks = conv tap shift on l
                    bf[nj][0]=Bs[kb*C2_BSW+n]; bf[nj][1]=Bs[(kb+4)*C2_BSW+n];
                }
                #pragma unroll
                for(int mi=0;mi<2;mi++)
                    #pragma unroll
                    for(int nj=0;nj<4;nj++)
                        MMA_F16(acc[mi][nj], af[mi], bf[nj]);
            }
        }
    }
    __syncthreads();

    float* red = smcf;   // [64][4]
    #pragma unroll
    for(int mi=0;mi<2;mi++){
        float m0=-FLT_MAX, m1=-FLT_MAX;
        #pragma unroll
        for(int nj=0;nj<4;nj++){
            m0=fmaxf(m0,fmaxf(acc[mi][nj][0],acc[mi][nj][1]));
            m1=fmaxf(m1,fmaxf(acc[mi][nj][2],acc[mi][nj][3]));
        }
        m0=fmaxf(m0,__shfl_xor_sync(0xFFFFFFFFu,m0,1));
        m0=fmaxf(m0,__shfl_xor_sync(0xFFFFFFFFu,m0,2));
        m1=fmaxf(m1,__shfl_xor_sync(0xFFFFFFFFu,m1,1));
        m1=fmaxf(m1,__shfl_xor_sync(0xFFFFFFFFu,m1,2));
        if(tg==0){
            red[(wm*32+mi*16+gg)*4+wn]   = m0;
            red[(wm*32+mi*16+gg+8)*4+wn] = m1;
        }
    }
    __syncthreads();
    if(t<64){
        float v=fmaxf(fmaxf(red[t*4],red[t*4+1]),fmaxf(red[t*4+2],red[t*4+3]));
        g_cnnp[((size_t)lh*ROWS + b*256+s)*256 + e0 + t] = v;
    }
}

// ---- fp16 MMA GEMM: tile 64x64 (R14 version, trailing sync kept) ----
#define HSW 72
#define H_AW (16*HSW)
#define H_STAGE (2*H_AW)
#define GEMM_SMEM (2*H_STAGE*4)

__device__ __forceinline__ void gemm_h_body(
    int N, int K, const float* __restrict__ A, const float* __restrict__ W,
    const float* __restrict__ bias, const float* __restrict__ res,
    float* __restrict__ C, int relu, uint32_t* sg)
{
    int t=threadIdx.x, lane=t&31, wid=t>>5;
    int gg=lane>>2, tg=lane&3;
    int wm=wid&1, wn=wid>>1;
    int m0=blockIdx.y<<6, n0=blockIdx.x<<6;
    int aRow=t>>2, aK=(t&3)*8;
    int bRow=t>>4, bCol=(t&15)*4;
    int S=K>>5;

    float4 rA0,rA1,rB0,rB1;
    rA0=*(const float4*)(A+(size_t)(m0+aRow)*K + aK);
    rA1=*(const float4*)(A+(size_t)(m0+aRow)*K + aK+4);
    rB0=*(const float4*)(W+(size_t)(2*bRow  )*N + n0+bCol);
    rB1=*(const float4*)(W+(size_t)(2*bRow+1)*N + n0+bCol);

    float acc[2][2][4];
    #pragma unroll
    for(int i=0;i<2;i++)
        #pragma unroll
        for(int j=0;j<2;j++)
            #pragma unroll
            for(int q=0;q<4;q++) acc[i][j][q]=0.f;

    int k2a = aK>>1;
    for(int s=0;s<S;s++){
        uint32_t* Asm = sg + (s&1)*H_STAGE;
        uint32_t* Bsm = Asm + H_AW;
        Asm[(k2a+0)*HSW+aRow]=h2pack(rA0.x, rA0.y);
        Asm[(k2a+1)*HSW+aRow]=h2pack(rA0.z, rA0.w);
        Asm[(k2a+2)*HSW+aRow]=h2pack(rA1.x, rA1.y);
        Asm[(k2a+3)*HSW+aRow]=h2pack(rA1.z, rA1.w);
        Bsm[bRow*HSW+bCol+0]=h2pack(rB0.x,rB1.x);
        Bsm[bRow*HSW+bCol+1]=h2pack(rB0.y,rB1.y);
        Bsm[bRow*HSW+bCol+2]=h2pack(rB0.z,rB1.z);
        Bsm[bRow*HSW+bCol+3]=h2pack(rB0.w,rB1.w);
        __syncthreads();
        if(s+1<S){
            int kk=(s+1)<<5;
            rA0=*(const float4*)(A+(size_t)(m0+aRow)*K + kk+aK);
            rA1=*(const float4*)(A+(size_t)(m0+aRow)*K + kk+aK+4);
            rB0=*(const float4*)(W+(size_t)(kk+2*bRow  )*N + n0+bCol);
            rB1=*(const float4*)(W+(size_t)(kk+2*bRow+1)*N + n0+bCol);
        }
        #pragma unroll
        for(int k4=0;k4<2;k4++){
            int kr=k4*8+tg;
            uint32_t af[2][4], bf[2][2];
            #pragma unroll
            for(int mi=0;mi<2;mi++){
                int e=wm*32+mi*16+gg;
                af[mi][0]=Asm[kr*HSW+e];     af[mi][1]=Asm[kr*HSW+e+8];
                af[mi][2]=Asm[(kr+4)*HSW+e]; af[mi][3]=Asm[(kr+4)*HSW+e+8];
            }
            #pragma unroll
            for(int nj=0;nj<2;nj++){
                int n=wn*16+nj*8+gg;
                bf[nj][0]=Bsm[kr*HSW+n]; bf[nj][1]=Bsm[(kr+4)*HSW+n];
            }
            #pragma unroll
            for(int mi=0;mi<2;mi++)
                #pragma unroll
                for(int nj=0;nj<2;nj++)
                    MMA_F16(acc[mi][nj], af[mi], bf[nj]);
        }
        __syncthreads();
    }

    #pragma unroll
    for(int mi=0;mi<2;mi++){
        #pragma unroll
        for(int nj=0;nj<2;nj++){
            int m=m0+wm*32+mi*16+gg;
            int n=n0+wn*16+nj*8+tg*2;
            #pragma unroll
            for(int q=0;q<4;q++){
                int mm=m+(q>>1)*8, nn=n+(q&1);
                float v=acc[mi][nj][q];
                if(bias) v+=bias[nn];
                if(res)  v+=res[(size_t)mm*N+nn];
                if(relu) v=fmaxf(v,0.f);
                C[(size_t)mm*N+nn]=v;
            }
        }
    }
}

__global__ __launch_bounds__(256) void gemm_h_kernel(
    int N,int K, const float* __restrict__ A, const float* __restrict__ W,
    const float* __restrict__ bias, const float* __restrict__ res,
    float* __restrict__ C, int relu)
{
    extern __shared__ uint32_t sgu[];
    gemm_h_body(N,K,A,W,bias,res,C,relu,sgu);
}

__global__ __launch_bounds__(256) void qkv_h_kernel(
    const float* __restrict__ A,
    const float* __restrict__ wq, const float* __restrict__ wk, const float* __restrict__ wv,
    const float* __restrict__ bq, const float* __restrict__ bk, const float* __restrict__ bv)
{
    extern __shared__ uint32_t sgu[];
    int z=blockIdx.z;
    const float* W=(z==0)?wq:(z==1)?wk:wv;
    const float* bias=(z==0)?bq:(z==1)?bk:bv;
    float* C=(z==0)?g_q:(z==1)?g_k:g_v;
    gemm_h_body(256,256,A,W,bias,nullptr,C,0,sgu);
}

// ---- layernorm; when cb2 != null, input = relu(max(cnnp halves) + cb2) ----
__global__ __launch_bounds__(256) void layernorm_kernel(
    const float* __restrict__ in, const float* __restrict__ gw, const float* __restrict__ bw,
    float* __restrict__ out, float* __restrict__ out2, float* __restrict__ sqout,
    const float* __restrict__ cb2)
{
    int row=blockIdx.x, t=threadIdx.x;
    float v;
    if(cb2){
        int sidx = row & 255;
        float p0 = g_cnnp[(size_t)row*256 + t];
        float p1 = g_cnnp[(size_t)ROWS*256 + (size_t)row*256 + t];
        v = fmaxf(fmaxf(p0,p1) + cb2[sidx*256 + t], 0.f);
    } else {
        v = in[row*256+t];
    }
    __shared__ float red[8];
    float su=warpSum(v);
    if((t&31)==0) red[t>>5]=su;
    __syncthreads();
    float tot=0.f;
    #pragma unroll
    for(int i=0;i<8;i++) tot+=red[i];
    float d=v - tot*(1.f/256.f);
    __syncthreads();
    float s2=warpSum(d*d);
    if((t&31)==0) red[t>>5]=s2;
    __syncthreads();
    float tot2=0.f;
    #pragma unroll
    for(int i=0;i<8;i++) tot2+=red[i];
    float y=d*rsqrtf(tot2*(1.f/256.f)+1e-5f);
    if(gw) y=y*gw[t]+bw[t];
    out[row*256+t]=y;
    if(out2) out2[row*256+t]=y;
    if(sqout){
        __syncthreads();
        float s3=warpSum(y*y);
        if((t&31)==0) red[t>>5]=s3;
        __syncthreads();
        if(t==0){
            float t3=0.f;
            #pragma unroll
            for(int i=0;i<8;i++) t3+=red[i];
            sqout[row]=t3;
        }
    }
}

// ---- tiled pairwise distance (Gram, 64x64) + global max ----
__global__ __launch_bounds__(256) void dist_tile_kernel(const float* __restrict__ feat)
{
    __shared__ float Fi[16*65], Fj[16*65], redm[8];
    int t=threadIdx.x, bx=blockIdx.x;
    int b=bx>>4, it=(bx>>2)&3, jt=bx&3;
    int tn=t&15, tm=t>>4;
    float acc[4][4];
    #pragma unroll
    for(int i=0;i<4;i++)
        #pragma unroll
        for(int j=0;j<4;j++) acc[i][j]=0.f;
    for(int k0=0;k0<256;k0+=16){
        #pragma unroll
        for(int i=0;i<4;i++){
            int lin=t+i*256, am=lin>>4, ak=lin&15;
            Fi[ak*65+am]=feat[(size_t)(b*256+it*64+am)*256+k0+ak];
            Fj[ak*65+am]=feat[(size_t)(b*256+jt*64+am)*256+k0+ak];
        }
        __syncthreads();
        #pragma unroll
        for(int k=0;k<16;k++){
            float av[4],bv[4];
            #pragma unroll
            for(int j=0;j<4;j++){ av[j]=Fi[k*65+tm*4+j]; bv[j]=Fj[k*65+tn*4+j]; }
            #pragma unroll
            for(int i=0;i<4;i++)
                #pragma unroll
                for(int j=0;j<4;j++) acc[i][j]=fmaf(av[i],bv[j],acc[i][j]);
        }
        __syncthreads();
    }
    float lm=0.f;
    #pragma unroll
    for(int i=0;i<4;i++){
        int ii=it*64+tm*4+i; float sqi=g_sq[b*256+ii];
        #pragma unroll
        for(int j=0;j<4;j++){
            int jj=jt*64+tn*4+j;
            float dv=sqrtf(fmaxf(sqi+g_sq[b*256+jj]-2.f*acc[i][j],0.f));
            g_dist[((size_t)(b*256+ii))*256+jj]=dv;
            lm=fmaxf(lm,dv);
        }
    }
    lm=warpMax(lm);
    if((t&31)==0) redm[t>>5]=lm;
    __syncthreads();
    if(t==0){
        float mm=redm[0];
        #pragma unroll
        for(int p=1;p<8;p++) mm=fmaxf(mm,redm[p]);
        atomicMax(&g_dmax,__float_as_uint(mm));
    }
}

// ---- fused attention (R14 64-row version) ----
#define ATT_SMEM ((64*36 + 256*36 + 256*36)*4)
__global__ __launch_bounds__(256) void attn_kernel(
    const float* __restrict__ q, const float* __restrict__ k, const float* __restrict__ v,
    const float* __restrict__ bw, const float* __restrict__ bb)
{
    extern __shared__ float sa[];
    float* qs = sa;
    float* ks = sa + 64*36;
    float* vs = ks + 256*36;
    int t=threadIdx.x, bx=blockIdx.x;
    int b=bx>>5, h=(bx>>2)&7, it=bx&3;
    int ti=t>>2, tj=t&3;
    int i=it*64+ti;

    for(int idx=t; idx<2048; idx+=256){
        int j=idx>>3, dc=idx&7;
        *(float4*)(ks + j*36 + dc*4) = *(const float4*)(k + (size_t)(b*256+j)*256 + h*32 + dc*4);
        *(float4*)(vs + j*36 + dc*4) = *(const float4*)(v + (size_t)(b*256+j)*256 + h*32 + dc*4);
    }
    for(int idx=t; idx<512; idx+=256){
        int r=idx>>3, dc=idx&7;
        *(float4*)(qs + r*36 + dc*4) = *(const float4*)(q + (size_t)(b*256+it*64+r)*256 + h*32 + dc*4);
    }
    __syncthreads();

    float qr[32];
    #pragma unroll
    for(int p=0;p<8;p++){
        float4 qv=*(const float4*)(qs + ti*36 + p*4);
        qr[p*4]=qv.x; qr[p*4+1]=qv.y; qr[p*4+2]=qv.z; qr[p*4+3]=qv.w;
    }

    float dmax=__uint_as_float(g_dmax);
    float inv=1.f/(dmax+1e-6f);
    float b0=bw[h], b1=bw[8+h], b2=bw[16+h], b3=bw[24+h];
    float ca=inv*(b0-b3);
    float cb=(b1-b2)*(1.f/255.f);
    float cst=b2+b3+bb[h];
    const float* drow = g_dist + ((size_t)(b*256+i))*256;

    float s[64];
    float mx=-FLT_MAX;
    #pragma unroll 4
    for(int jj=0;jj<64;jj++){
        int j=jj*4+tj;
        float sc=0.f;
        const float* kr=ks+j*36;
        #pragma unroll
        for(int p=0;p<8;p++){
            float4 kv=*(const float4*)(kr+p*4);
            sc=fmaf(qr[p*4],kv.x,sc);   sc=fmaf(qr[p*4+1],kv.y,sc);
            sc=fmaf(qr[p*4+2],kv.z,sc); sc=fmaf(qr[p*4+3],kv.w,sc);
        }
        sc*=0.17677669529663687f;
        sc += drow[j]*ca + fabsf((float)(i-j))*cb + cst;
        s[jj]=sc;
        mx=fmaxf(mx,sc);
    }
    mx=fmaxf(mx,__shfl_xor_sync(0xFFFFFFFFu,mx,1));
    mx=fmaxf(mx,__shfl_xor_sync(0xFFFFFFFFu,mx,2));
    float sum=0.f;
    #pragma unroll
    for(int jj=0;jj<64;jj++){ s[jj]=expf(s[jj]-mx); sum+=s[jj]; }
    sum+=__shfl_xor_sync(0xFFFFFFFFu,sum,1);
    sum+=__shfl_xor_sync(0xFFFFFFFFu,sum,2);
    float rs=1.f/sum;

    float o[32];
    #pragma unroll
    for(int d=0;d<32;d++) o[d]=0.f;
    #pragma unroll 4
    for(int jj=0;jj<64;jj++){
        float sv=s[jj]*rs;
        const float* vr=vs+(jj*4+tj)*36;
        #pragma unroll
        for(int p=0;p<8;p++){
            float4 vv=*(const float4*)(vr+p*4);
            o[p*4]  =fmaf(sv,vv.x,o[p*4]);   o[p*4+1]=fmaf(sv,vv.y,o[p*4+1]);
            o[p*4+2]=fmaf(sv,vv.z,o[p*4+2]); o[p*4+3]=fmaf(sv,vv.w,o[p*4+3]);
        }
    }
    #pragma unroll
    for(int d=0;d<32;d++){
        o[d]+=__shfl_xor_sync(0xFFFFFFFFu,o[d],1);
        o[d]+=__shfl_xor_sync(0xFFFFFFFFu,o[d],2);
    }
    if(tj==0){
        float* orow = g_attno + (size_t)(b*256+i)*256 + h*32;
        #pragma unroll
        for(int p=0;p<8;p++)
            *(float4*)(orow+p*4) = make_float4(o[p*4],o[p*4+1],o[p*4+2],o[p*4+3]);
    }
}

__global__ __launch_bounds__(256) void pool_kernel(float* __restrict__ pooled_out)
{
    int blk=blockIdx.x, b=blk>>3, ns=blk&7, t=threadIdx.x;
    float mx=-FLT_MAX;
    #pragma unroll 4
    for(int si=0;si<32;si++)
        mx=fmaxf(mx,g_h[(size_t)(b*256+ns*32+si)*256+t]);
    pooled_out[b*2048+ns*256+t]=mx;
}

__global__ __launch_bounds__(256) void fc_kernel(
    const float* __restrict__ pooled, const float* __restrict__ fw,
    const float* __restrict__ fb, float* __restrict__ out)
{
    int b=blockIdx.x, t=threadIdx.x;
    float a0=0.f,a1=0.f;
    for(int kk=t;kk<2048;kk+=256){
        float p=pooled[b*2048+kk];
        a0=fmaf(p,fw[kk*2+0],a0); a1=fmaf(p,fw[kk*2+1],a1);
    }
    __shared__ float r0[8],r1[8];
    a0=warpSum(a0); a1=warpSum(a1);
    if((t&31)==0){ r0[t>>5]=a0; r1[t>>5]=a1; }
    __syncthreads();
    if(t==0){
        float s0=0.f,s1=0.f;
        #pragma unroll
        for(int p=0;p<8;p++){ s0+=r0[p]; s1+=r1[p]; }
        out[b*2+0]=s0+fb[0]; out[b*2+1]=s1+fb[1];
    }
}

extern "C" void kernel_launch(void* const* d_in, const int* in_sizes, int n_in,
                              void* d_out, int out_size)
{
    const float* x=(const float*)d_in[0];
    const float* conv1_w=(const float*)d_in[1];
    const float* conv1_b=(const float*)d_in[2];
    const float* conv2_w=(const float*)d_in[3];
    const float* conv2_b=(const float*)d_in[4];
    const float* ln1_g=(const float*)d_in[5];
    const float* ln1_b=(const float*)d_in[6];
    const float* wq=(const float*)d_in[7];
    const float* bq=(const float*)d_in[8];
    const float* wk=(const float*)d_in[9];
    const float* bk=(const float*)d_in[10];
    const float* wv=(const float*)d_in[11];
    const float* bv=(const float*)d_in[12];
    const float* wo=(const float*)d_in[13];
    const float* bo=(const float*)d_in[14];
    const float* bias_w=(const float*)d_in[15];
    const float* bias_b=(const float*)d_in[16];
    const float* ln2_g=(const float*)d_in[17];
    const float* ln2_b=(const float*)d_in[18];
    const float* ffn_w1=(const float*)d_in[19];
    const float* ffn_b1=(const float*)d_in[20];
    const float* ffn_w2=(const float*)d_in[21];
    const float* ffn_b2=(const float*)d_in[22];
    const float* fc_w=(const float*)d_in[23];
    const float* fc_b=(const float*)d_in[24];
    float* out=(float*)d_out;

    float *p_feat,*p_h,*p_hn,*p_attno,*p_ffn,*p_sq,*p_q,*p_k,*p_v,*p_pool;
    cudaGetSymbolAddress((void**)&p_feat,g_feat);
    cudaGetSymbolAddress((void**)&p_h,g_h);
    cudaGetSymbolAddress((void**)&p_hn,g_hn);
    cudaGetSymbolAddress((void**)&p_attno,g_attno);
    cudaGetSymbolAddress((void**)&p_ffn,g_ffn);
    cudaGetSymbolAddress((void**)&p_sq,g_sq);
    cudaGetSymbolAddress((void**)&p_q,g_q);
    cudaGetSymbolAddress((void**)&p_k,g_k);
    cudaGetSymbolAddress((void**)&p_v,g_v);
    cudaGetSymbolAddress((void**)&p_pool,g_pooled);

    cudaFuncSetAttribute(conv2_mma_kernel,
                         cudaFuncAttributeMaxDynamicSharedMemorySize, CONV2_SMEM_BYTES);
    cudaFuncSetAttribute(attn_kernel,
                         cudaFuncAttributeMaxDynamicSharedMemorySize, ATT_SMEM);
    cudaFuncSetAttribute(gemm_h_kernel,
                         cudaFuncAttributeMaxDynamicSharedMemorySize, GEMM_SMEM);
    cudaFuncSetAttribute(qkv_h_kernel,
                         cudaFuncAttributeMaxDynamicSharedMemorySize, GEMM_SMEM);

    init_kernel<<<1,32>>>();
    conv1_kernel<<<2048,256>>>(x, conv1_w, conv1_b);
    w2p_kernel<<<2048,256>>>(conv2_w);
    conv2_mma_kernel<<<16384,256,CONV2_SMEM_BYTES>>>();
    layernorm_kernel<<<ROWS,256>>>(nullptr, nullptr, nullptr, p_feat, p_h, p_sq, conv2_b);
    dist_tile_kernel<<<128,256>>>(p_feat);

    dim3 g256(4,32), g512(8,32), gqkv(4,32,3);
    for(int l=0;l<2;l++){
        layernorm_kernel<<<ROWS,256>>>(p_h, ln1_g+l*256, ln1_b+l*256, p_hn, nullptr, nullptr, nullptr);
        qkv_h_kernel<<<gqkv,256,GEMM_SMEM>>>(p_hn, wq+l*65536, wk+l*65536, wv+l*65536,
                                             bq+l*256, bk+l*256, bv+l*256);
        attn_kernel<<<256,256,ATT_SMEM>>>(p_q, p_k, p_v, bias_w+l*32, bias_b+l*8);
        gemm_h_kernel<<<g256,256,GEMM_SMEM>>>(256,256, p_attno, wo+l*65536, bo+l*256, p_h, p_h, 0);
        layernorm_kernel<<<ROWS,256>>>(p_h, ln2_g+l*256, ln2_b+l*256, p_hn, nullptr, nullptr, nullptr);
        gemm_h_kernel<<<g512,256,GEMM_SMEM>>>(512,256, p_hn, ffn_w1+l*131072, ffn_b1+l*512, nullptr, p_ffn, 1);
        gemm_h_kernel<<<g256,256,GEMM_SMEM>>>(256,512, p_ffn, ffn_w2+l*131072, ffn_b2+l*256, p_h, p_h, 0);
    }
    pool_kernel<<<64,256>>>(p_pool);
    fc_kernel<<<8,256>>>(p_pool, fc_w, fc_b, out);
}

// round 17
// speedup vs baseline: 1.0699x; 1.0699x over previous
#include <cuda_runtime.h>
#include <cuda_fp16.h>
#include <math.h>
#include <cfloat>
#include <stdint.h>

#define Bv 8
#define Sv 256
#define Ev 256
#define Hv 8
#define ROWS (Bv*Sv)

__device__ float g_cnn[ROWS*Ev];
__device__ float g_feat[ROWS*Ev];
__device__ float g_h[ROWS*Ev];
__device__ float g_hn[ROWS*Ev];
__device__ float g_q[ROWS*Ev];
__device__ float g_k[ROWS*Ev];
__device__ float g_v[ROWS*Ev];
__device__ float g_attno[ROWS*Ev];
__device__ float g_ffn[ROWS*2*Ev];
__device__ float g_dist[Bv*Sv*Sv];
__device__ float g_sq[ROWS];
__device__ float g_pooled[Bv*8*Ev];
__device__ unsigned g_dmax;
__device__ uint32_t g_h1q[(size_t)2048*64*264];     // [sb][c2][l padded 264] half2
__device__ uint32_t g_w2p[(size_t)256*192*256];     // [s][k2=ks*64+c2][e] half2

__device__ __forceinline__ float warpSum(float v){
    #pragma unroll
    for(int o=16;o>0;o>>=1) v += __shfl_xor_sync(0xFFFFFFFFu,v,o);
    return v;
}
__device__ __forceinline__ float warpMax(float v){
    #pragma unroll
    for(int o=16;o>0;o>>=1) v = fmaxf(v,__shfl_xor_sync(0xFFFFFFFFu,v,o));
    return v;
}
__device__ __forceinline__ void cpa16(void* sm, const void* g){
    unsigned sa = (unsigned)__cvta_generic_to_shared(sm);
    asm volatile("cp.async.cg.shared.global [%0], [%1], 16;" :: "r"(sa), "l"(g));
}
#define CP_COMMIT() asm volatile("cp.async.commit_group;")
#define CP_WAIT(N)  asm volatile("cp.async.wait_group %0;" :: "n"(N))
#define MMA_F16(C,A,B) \
    asm volatile("mma.sync.aligned.m16n8k16.row.col.f32.f16.f16.f32 " \
        "{%0,%1,%2,%3},{%4,%5,%6,%7},{%8,%9},{%0,%1,%2,%3};" \
        : "+f"((C)[0]),"+f"((C)[1]),"+f"((C)[2]),"+f"((C)[3]) \
        : "r"((A)[0]),"r"((A)[1]),"r"((A)[2]),"r"((A)[3]),"r"((B)[0]),"r"((B)[1]))

__device__ __forceinline__ uint32_t h2pack(float a, float b){
    __half2 h = __floats2half2_rn(a,b);
    return *(uint32_t*)&h;
}

__global__ void init_kernel(){ if(threadIdx.x==0) g_dmax=0u; }

// ---- conv1 -> g_h1q packed half2 [sb][c2][264], zero pads at l=0, 257..263 ----
__global__ __launch_bounds__(256) void conv1_kernel(
    const float* __restrict__ x, const float* __restrict__ w1, const float* __restrict__ b1)
{
    __shared__ float xs[4*258], w1s[1536], b1s[128];
    int t=threadIdx.x, sb=blockIdx.x, s=sb>>3, b=sb&7;
    for(int idx=t; idx<4*258; idx+=256){
        int ci=idx/258, p=idx-ci*258; float v=0.f;
        if(p>=1 && p<=256) v = x[((b*Sv+s)*4+ci)*256 + p-1];
        xs[idx]=v;
    }
    for(int idx=t; idx<1536; idx+=256) w1s[idx]=w1[s*1536+idx];
    if(t<128) b1s[t]=b1[s*128+t];
    __syncthreads();
    for(int idx=t; idx<64*256; idx+=256){
        int c2=idx>>8, l=idx&255;
        float a0=b1s[2*c2], a1=b1s[2*c2+1];
        const float* w0=&w1s[(2*c2)*12];
        const float* w1r=&w1s[(2*c2+1)*12];
        #pragma unroll
        for(int ci=0;ci<4;ci++){
            const float* xr=&xs[ci*258+l];
            a0=fmaf(xr[0],w0[ci*3+0],a0); a0=fmaf(xr[1],w0[ci*3+1],a0); a0=fmaf(xr[2],w0[ci*3+2],a0);
            a1=fmaf(xr[0],w1r[ci*3+0],a1); a1=fmaf(xr[1],w1r[ci*3+1],a1); a1=fmaf(xr[2],w1r[ci*3+2],a1);
        }
        g_h1q[((size_t)sb*64 + c2)*264 + l + 1] = h2pack(fmaxf(a0,0.f), fmaxf(a1,0.f));
    }
    for(int idx=t; idx<64*8; idx+=256){
        int c2=idx>>3, q=idx&7, p=(q==0)?0:(256+q);
        g_h1q[((size_t)sb*64+c2)*264 + p]=0u;
    }
}

// ---- w2 -> g_w2p packed half2 [s][k2=ks*64+c2][e] ----
__global__ __launch_bounds__(256) void w2p_kernel(const float* __restrict__ w2)
{
    int t=threadIdx.x, bx=blockIdx.x;
    int s=bx>>3, part=bx&7;
    for(int i=t;i<6144;i+=256){
        int j = part*6144 + i;
        int k2 = j>>8, e = j&255;
        int ks = k2>>6, c2 = k2&63;
        const float* src = w2 + ((size_t)(s*256+e))*384;
        g_w2p[((size_t)s*192 + k2)*256 + e] = h2pack(src[(2*c2)*3+ks], src[(2*c2+1)*3+ks]);
    }
}

// ---- conv2 fp16 MMA GEMM, 2 stages with split-commit prologue (R14) ----
#define ASW 136
#define BSW 264
#define A_WORDS (96*ASW)
#define STAGE_WORDS (A_WORDS + 32*BSW)
#define CONV2_SMEM_BYTES (2*STAGE_WORDS*4)

__global__ __launch_bounds__(256,1) void conv2_mma_kernel(const float* __restrict__ b2)
{
    extern __shared__ float smcf[];
    uint32_t* smc = (uint32_t*)smcf;
    int t=threadIdx.x, bx=blockIdx.x;
    int s=bx>>4, eh=(bx>>3)&1, b=bx&7, sb=s*8+b;
    int lane=t&31, wid=t>>5, gg=lane>>2, tg=lane&3;
    int wm=wid&1, wn=wid>>1, e0=eh*128;
    const uint32_t* Ag = g_w2p + (size_t)s*192*256 + e0;
    const uint32_t* Bg = g_h1q + (size_t)sb*64*264;

    float acc[4][8][4];
    #pragma unroll
    for(int i=0;i<4;i++)
        #pragma unroll
        for(int j=0;j<8;j++)
            #pragma unroll
            for(int q=0;q<4;q++) acc[i][j][q]=0.f;

    #define LOAD_B(cc,buf) do{                                             \
        uint32_t* Bs_ = smc + (buf)*STAGE_WORDS + A_WORDS;                  \
        _Pragma("unroll")                                                   \
        for(int i=0;i<9;i++){                                               \
            int idx=t+i*256;                                                \
            if(idx<2112){                                                   \
                int r=idx/66, f=idx-r*66;                                   \
                cpa16(Bs_+r*BSW+f*4, Bg+((size_t)((cc)*32+r))*264+f*4);     \
            }                                                               \
        }                                                                   \
    }while(0)
    #define LOAD_A_KS(cc,buf,ksv) do{                                      \
        uint32_t* As_ = smc + (buf)*STAGE_WORDS;                            \
        _Pragma("unroll")                                                   \
        for(int i=0;i<4;i++){                                               \
            int idx=t+i*256, r=idx>>5, f=idx&31;                            \
            cpa16(As_+((ksv)*32+r)*ASW+f*4,                                 \
                  Ag+((size_t)((ksv)*64+(cc)*32+r))*256+f*4);               \
        }                                                                   \
    }while(0)
    #define COMPUTE_KS(Asu,Bsu,ksv) do{                                     \
        _Pragma("unroll")                                                   \
        for(int kk=0; kk<4; kk++){                                          \
            int kr = (ksv)*32 + kk*8 + tg;                                  \
            int kb = kk*8 + tg;                                             \
            uint32_t af[4][4];                                              \
            _Pragma("unroll")                                               \
            for(int mi=0;mi<4;mi++){                                        \
                int e = wm*64 + mi*16 + gg;                                 \
                af[mi][0]=(Asu)[kr*ASW+e];     af[mi][1]=(Asu)[kr*ASW+e+8]; \
                af[mi][2]=(Asu)[(kr+4)*ASW+e]; af[mi][3]=(Asu)[(kr+4)*ASW+e+8];\
            }                                                               \
            uint32_t bf[8][2];                                              \
            _Pragma("unroll")                                               \
            for(int nj=0;nj<8;nj++){                                        \
                int n = (ksv) + wn*64 + nj*8 + gg;                          \
                bf[nj][0]=(Bsu)[kb*BSW+n]; bf[nj][1]=(Bsu)[(kb+4)*BSW+n];   \
            }                                                               \
            _Pragma("unroll")                                               \
            for(int mi=0;mi<4;mi++)                                         \
                _Pragma("unroll")                                           \
                for(int nj=0;nj<8;nj++)                                     \
                    MMA_F16(acc[mi][nj], af[mi], bf[nj]);                   \
        }                                                                   \
    }while(0)

    LOAD_B(0,0); LOAD_A_KS(0,0,0); CP_COMMIT();
    LOAD_A_KS(0,0,1); LOAD_A_KS(0,0,2); CP_COMMIT();
    LOAD_B(1,1); LOAD_A_KS(1,1,0); LOAD_A_KS(1,1,1); LOAD_A_KS(1,1,2); CP_COMMIT();

    const uint32_t* A0 = smc;
    const uint32_t* B0 = smc + A_WORDS;
    const uint32_t* A1 = smc + STAGE_WORDS;
    const uint32_t* B1 = A1 + A_WORDS;

    CP_WAIT(2); __syncthreads();
    COMPUTE_KS(A0,B0,0);
    CP_WAIT(1); __syncthreads();
    COMPUTE_KS(A0,B0,1);
    COMPUTE_KS(A0,B0,2);
    CP_WAIT(0); __syncthreads();
    COMPUTE_KS(A1,B1,0);
    COMPUTE_KS(A1,B1,1);
    COMPUTE_KS(A1,B1,2);
    __syncthreads();

    float* red = smcf;   // [128][4]
    #pragma unroll
    for(int mi=0;mi<4;mi++){
        float m0=-FLT_MAX, m1=-FLT_MAX;
        #pragma unroll
        for(int nj=0;nj<8;nj++){
            m0=fmaxf(m0,fmaxf(acc[mi][nj][0],acc[mi][nj][1]));
            m1=fmaxf(m1,fmaxf(acc[mi][nj][2],acc[mi][nj][3]));
        }
        m0=fmaxf(m0,__shfl_xor_sync(0xFFFFFFFFu,m0,1));
        m0=fmaxf(m0,__shfl_xor_sync(0xFFFFFFFFu,m0,2));
        m1=fmaxf(m1,__shfl_xor_sync(0xFFFFFFFFu,m1,1));
        m1=fmaxf(m1,__shfl_xor_sync(0xFFFFFFFFu,m1,2));
        if(tg==0){
            red[(wm*64+mi*16+gg)*4+wn]   = m0;
            red[(wm*64+mi*16+gg+8)*4+wn] = m1;
        }
    }
    __syncthreads();
    if(t<128){
        float v=fmaxf(fmaxf(red[t*4],red[t*4+1]),fmaxf(red[t*4+2],red[t*4+3]));
        g_cnn[(b*Sv+s)*Ev + e0 + t] = fmaxf(v + b2[s*256+e0+t], 0.f);
    }
}

// ---- fp16 MMA GEMM: tile 64x64; single sync per stage (double-buffered) ----
#define HSW 72
#define H_AW (16*HSW)
#define H_STAGE (2*H_AW)
#define GEMM_SMEM (2*H_STAGE*4)

__device__ __forceinline__ void gemm_h_body(
    int N, int K, const float* __restrict__ A, const float* __restrict__ W,
    const float* __restrict__ bias, const float* __restrict__ res,
    float* __restrict__ C, int relu, uint32_t* sg)
{
    int t=threadIdx.x, lane=t&31, wid=t>>5;
    int gg=lane>>2, tg=lane&3;
    int wm=wid&1, wn=wid>>1;
    int m0=blockIdx.y<<6, n0=blockIdx.x<<6;
    int aRow=t>>2, aK=(t&3)*8;
    int bRow=t>>4, bCol=(t&15)*4;
    int S=K>>5;

    float4 rA0,rA1,rB0,rB1;
    rA0=*(const float4*)(A+(size_t)(m0+aRow)*K + aK);
    rA1=*(const float4*)(A+(size_t)(m0+aRow)*K + aK+4);
    rB0=*(const float4*)(W+(size_t)(2*bRow  )*N + n0+bCol);
    rB1=*(const float4*)(W+(size_t)(2*bRow+1)*N + n0+bCol);

    float acc[2][2][4];
    #pragma unroll
    for(int i=0;i<2;i++)
        #pragma unroll
        for(int j=0;j<2;j++)
            #pragma unroll
            for(int q=0;q<4;q++) acc[i][j][q]=0.f;

    int k2a = aK>>1;
    for(int s=0;s<S;s++){
        uint32_t* Asm = sg + (s&1)*H_STAGE;
        uint32_t* Bsm = Asm + H_AW;
        Asm[(k2a+0)*HSW+aRow]=h2pack(rA0.x, rA0.y);
        Asm[(k2a+1)*HSW+aRow]=h2pack(rA0.z, rA0.w);
        Asm[(k2a+2)*HSW+aRow]=h2pack(rA1.x, rA1.y);
        Asm[(k2a+3)*HSW+aRow]=h2pack(rA1.z, rA1.w);
        Bsm[bRow*HSW+bCol+0]=h2pack(rB0.x,rB1.x);
        Bsm[bRow*HSW+bCol+1]=h2pack(rB0.y,rB1.y);
        Bsm[bRow*HSW+bCol+2]=h2pack(rB0.z,rB1.z);
        Bsm[bRow*HSW+bCol+3]=h2pack(rB0.w,rB1.w);
        __syncthreads();
        if(s+1<S){
            int kk=(s+1)<<5;
            rA0=*(const float4*)(A+(size_t)(m0+aRow)*K + kk+aK);
            rA1=*(const float4*)(A+(size_t)(m0+aRow)*K + kk+aK+4);
            rB0=*(const float4*)(W+(size_t)(kk+2*bRow  )*N + n0+bCol);
            rB1=*(const float4*)(W+(size_t)(kk+2*bRow+1)*N + n0+bCol);
        }
        #pragma unroll
        for(int k4=0;k4<2;k4++){
            int kr=k4*8+tg;
            uint32_t af[2][4], bf[2][2];
            #pragma unroll
            for(int mi=0;mi<2;mi++){
                int e=wm*32+mi*16+gg;
                af[mi][0]=Asm[kr*HSW+e];     af[mi][1]=Asm[kr*HSW+e+8];
                af[mi][2]=Asm[(kr+4)*HSW+e]; af[mi][3]=Asm[(kr+4)*HSW+e+8];
            }
            #pragma unroll
            for(int nj=0;nj<2;nj++){
                int n=wn*16+nj*8+gg;
                bf[nj][0]=Bsm[kr*HSW+n]; bf[nj][1]=Bsm[(kr+4)*HSW+n];
            }
            #pragma unroll
            for(int mi=0;mi<2;mi++)
                #pragma unroll
                for(int nj=0;nj<2;nj++)
                    MMA_F16(acc[mi][nj], af[mi], bf[nj]);
        }
        // no trailing sync: double-buffered; next iter writes the other buffer,
        // and its mid-sync orders this compute before buffer reuse at s+2.
    }

    #pragma unroll
    for(int mi=0;mi<2;mi++){
        #pragma unroll
        for(int nj=0;nj<2;nj++){
            int m=m0+wm*32+mi*16+gg;
            int n=n0+wn*16+nj*8+tg*2;
            #pragma unroll
            for(int q=0;q<4;q++){
                int mm=m+(q>>1)*8, nn=n+(q&1);
                float v=acc[mi][nj][q];
                if(bias) v+=bias[nn];
                if(res)  v+=res[(size_t)mm*N+nn];
                if(relu) v=fmaxf(v,0.f);
                C[(size_t)mm*N+nn]=v;
            }
        }
    }
}

__global__ __launch_bounds__(256) void gemm_h_kernel(
    int N,int K, const float* __restrict__ A, const float* __restrict__ W,
    const float* __restrict__ bias, const float* __restrict__ res,
    float* __restrict__ C, int relu)
{
    extern __shared__ uint32_t sgu[];
    gemm_h_body(N,K,A,W,bias,res,C,relu,sgu);
}

__global__ __launch_bounds__(256) void qkv_h_kernel(
    const float* __restrict__ A,
    const float* __restrict__ wq, const float* __restrict__ wk, const float* __restrict__ wv,
    const float* __restrict__ bq, const float* __restrict__ bk, const float* __restrict__ bv)
{
    extern __shared__ uint32_t sgu[];
    int z=blockIdx.z;
    const float* W=(z==0)?wq:(z==1)?wk:wv;
    const float* bias=(z==0)?bq:(z==1)?bk:bv;
    float* C=(z==0)?g_q:(z==1)?g_k:g_v;
    gemm_h_body(256,256,A,W,bias,nullptr,C,0,sgu);
}

// ---- layernorm (optional affine / dup-out / sq-norm-out) ----
__global__ __launch_bounds__(256) void layernorm_kernel(
    const float* __restrict__ in, const float* __restrict__ gw, const float* __restrict__ bw,
    float* __restrict__ out, float* __restrict__ out2, float* __restrict__ sqout)
{
    int row=blockIdx.x, t=threadIdx.x;
    float v=in[row*256+t];
    __shared__ float red[8];
    float su=warpSum(v);
    if((t&31)==0) red[t>>5]=su;
    __syncthreads();
    float tot=0.f;
    #pragma unroll
    for(int i=0;i<8;i++) tot+=red[i];
    float d=v - tot*(1.f/256.f);
    __syncthreads();
    float s2=warpSum(d*d);
    if((t&31)==0) red[t>>5]=s2;
    __syncthreads();
    float tot2=0.f;
    #pragma unroll
    for(int i=0;i<8;i++) tot2+=red[i];
    float y=d*rsqrtf(tot2*(1.f/256.f)+1e-5f);
    if(gw) y=y*gw[t]+bw[t];
    out[row*256+t]=y;
    if(out2) out2[row*256+t]=y;
    if(sqout){
        __syncthreads();
        float s3=warpSum(y*y);
        if((t&31)==0) red[t>>5]=s3;
        __syncthreads();
        if(t==0){
            float t3=0.f;
            #pragma unroll
            for(int i=0;i<8;i++) t3+=red[i];
            sqout[row]=t3;
        }
    }
}

// ---- tiled pairwise distance (Gram) + global max ----
__global__ __launch_bounds__(256) void dist_tile_kernel(const float* __restrict__ feat)
{
    __shared__ float Fi[16*65], Fj[16*65], redm[8];
    int t=threadIdx.x, bx=blockIdx.x;
    int b=bx>>4, it=(bx>>2)&3, jt=bx&3;
    int tn=t&15, tm=t>>4;
    float acc[4][4];
    #pragma unroll
    for(int i=0;i<4;i++)
        #pragma unroll
        for(int j=0;j<4;j++) acc[i][j]=0.f;
    for(int k0=0;k0<256;k0+=16){
        #pragma unroll
        for(int i=0;i<4;i++){
            int lin=t+i*256, am=lin>>4, ak=lin&15;
            Fi[ak*65+am]=feat[(size_t)(b*256+it*64+am)*256+k0+ak];
            Fj[ak*65+am]=feat[(size_t)(b*256+jt*64+am)*256+k0+ak];
        }
        __syncthreads();
        #pragma unroll
        for(int k=0;k<16;k++){
            float av[4],bv[4];
            #pragma unroll
            for(int j=0;j<4;j++){ av[j]=Fi[k*65+tm*4+j]; bv[j]=Fj[k*65+tn*4+j]; }
            #pragma unroll
            for(int i=0;i<4;i++)
                #pragma unroll
                for(int j=0;j<4;j++) acc[i][j]=fmaf(av[i],bv[j],acc[i][j]);
        }
        __syncthreads();
    }
    float lm=0.f;
    #pragma unroll
    for(int i=0;i<4;i++){
        int ii=it*64+tm*4+i; float sqi=g_sq[b*256+ii];
        #pragma unroll
        for(int j=0;j<4;j++){
            int jj=jt*64+tn*4+j;
            float dv=sqrtf(fmaxf(sqi+g_sq[b*256+jj]-2.f*acc[i][j],0.f));
            g_dist[((size_t)(b*256+ii))*256+jj]=dv;
            lm=fmaxf(lm,dv);
        }
    }
    lm=warpMax(lm);
    if((t&31)==0) redm[t>>5]=lm;
    __syncthreads();
    if(t==0){
        float mm=redm[0];
        #pragma unroll
        for(int p=1;p<8;p++) mm=fmaxf(mm,redm[p]);
        atomicMax(&g_dmax,__float_as_uint(mm));
    }
}

// ---- fused attention (R14 64-row version) ----
#define ATT_SMEM ((64*36 + 256*36 + 256*36)*4)
__global__ __launch_bounds__(256) void attn_kernel(
    const float* __restrict__ q, const float* __restrict__ k, const float* __restrict__ v,
    const float* __restrict__ bw, const float* __restrict__ bb)
{
    extern __shared__ float sa[];
    float* qs = sa;
    float* ks = sa + 64*36;
    float* vs = ks + 256*36;
    int t=threadIdx.x, bx=blockIdx.x;
    int b=bx>>5, h=(bx>>2)&7, it=bx&3;
    int ti=t>>2, tj=t&3;
    int i=it*64+ti;

    for(int idx=t; idx<2048; idx+=256){
        int j=idx>>3, dc=idx&7;
        *(float4*)(ks + j*36 + dc*4) = *(const float4*)(k + (size_t)(b*256+j)*256 + h*32 + dc*4);
        *(float4*)(vs + j*36 + dc*4) = *(const float4*)(v + (size_t)(b*256+j)*256 + h*32 + dc*4);
    }
    for(int idx=t; idx<512; idx+=256){
        int r=idx>>3, dc=idx&7;
        *(float4*)(qs + r*36 + dc*4) = *(const float4*)(q + (size_t)(b*256+it*64+r)*256 + h*32 + dc*4);
    }
    __syncthreads();

    float qr[32];
    #pragma unroll
    for(int p=0;p<8;p++){
        float4 qv=*(const float4*)(qs + ti*36 + p*4);
        qr[p*4]=qv.x; qr[p*4+1]=qv.y; qr[p*4+2]=qv.z; qr[p*4+3]=qv.w;
    }

    float dmax=__uint_as_float(g_dmax);
    float inv=1.f/(dmax+1e-6f);
    float b0=bw[h], b1=bw[8+h], b2=bw[16+h], b3=bw[24+h];
    float ca=inv*(b0-b3);
    float cb=(b1-b2)*(1.f/255.f);
    float cst=b2+b3+bb[h];
    const float* drow = g_dist + ((size_t)(b*256+i))*256;

    float s[64];
    float mx=-FLT_MAX;
    #pragma unroll 4
    for(int jj=0;jj<64;jj++){
        int j=jj*4+tj;
        float sc=0.f;
        const float* kr=ks+j*36;
        #pragma unroll
        for(int p=0;p<8;p++){
            float4 kv=*(const float4*)(kr+p*4);
            sc=fmaf(qr[p*4],kv.x,sc);   sc=fmaf(qr[p*4+1],kv.y,sc);
            sc=fmaf(qr[p*4+2],kv.z,sc); sc=fmaf(qr[p*4+3],kv.w,sc);
        }
        sc*=0.17677669529663687f;
        sc += drow[j]*ca + fabsf((float)(i-j))*cb + cst;
        s[jj]=sc;
        mx=fmaxf(mx,sc);
    }
    mx=fmaxf(mx,__shfl_xor_sync(0xFFFFFFFFu,mx,1));
    mx=fmaxf(mx,__shfl_xor_sync(0xFFFFFFFFu,mx,2));
    float sum=0.f;
    #pragma unroll
    for(int jj=0;jj<64;jj++){ s[jj]=expf(s[jj]-mx); sum+=s[jj]; }
    sum+=__shfl_xor_sync(0xFFFFFFFFu,sum,1);
    sum+=__shfl_xor_sync(0xFFFFFFFFu,sum,2);
    float rs=1.f/sum;

    float o[32];
    #pragma unroll
    for(int d=0;d<32;d++) o[d]=0.f;
    #pragma unroll 4
    for(int jj=0;jj<64;jj++){
        float sv=s[jj]*rs;
        const float* vr=vs+(jj*4+tj)*36;
        #pragma unroll
        for(int p=0;p<8;p++){
            float4 vv=*(const float4*)(vr+p*4);
            o[p*4]  =fmaf(sv,vv.x,o[p*4]);   o[p*4+1]=fmaf(sv,vv.y,o[p*4+1]);
            o[p*4+2]=fmaf(sv,vv.z,o[p*4+2]); o[p*4+3]=fmaf(sv,vv.w,o[p*4+3]);
        }
    }
    #pragma unroll
    for(int d=0;d<32;d++){
        o[d]+=__shfl_xor_sync(0xFFFFFFFFu,o[d],1);
        o[d]+=__shfl_xor_sync(0xFFFFFFFFu,o[d],2);
    }
    if(tj==0){
        float* orow = g_attno + (size_t)(b*256+i)*256 + h*32;
        #pragma unroll
        for(int p=0;p<8;p++)
            *(float4*)(orow+p*4) = make_float4(o[p*4],o[p*4+1],o[p*4+2],o[p*4+3]);
    }
}

__global__ __launch_bounds__(256) void pool_kernel(float* __restrict__ pooled_out)
{
    int blk=blockIdx.x, b=blk>>3, ns=blk&7, t=threadIdx.x;
    float mx=-FLT_MAX;
    #pragma unroll 4
    for(int si=0;si<32;si++)
        mx=fmaxf(mx,g_h[(size_t)(b*256+ns*32+si)*256+t]);
    pooled_out[b*2048+ns*256+t]=mx;
}

__global__ __launch_bounds__(256) void fc_kernel(
    const float* __restrict__ pooled, const float* __restrict__ fw,
    const float* __restrict__ fb, float* __restrict__ out)
{
    int b=blockIdx.x, t=threadIdx.x;
    float a0=0.f,a1=0.f;
    for(int kk=t;kk<2048;kk+=256){
        float p=pooled[b*2048+kk];
        a0=fmaf(p,fw[kk*2+0],a0); a1=fmaf(p,fw[kk*2+1],a1);
    }
    __shared__ float r0[8],r1[8];
    a0=warpSum(a0); a1=warpSum(a1);
    if((t&31)==0){ r0[t>>5]=a0; r1[t>>5]=a1; }
    __syncthreads();
    if(t==0){
        float s0=0.f,s1=0.f;
        #pragma unroll
        for(int p=0;p<8;p++){ s0+=r0[p]; s1+=r1[p]; }
        out[b*2+0]=s0+fb[0]; out[b*2+1]=s1+fb[1];
    }
}

extern "C" void kernel_launch(void* const* d_in, const int* in_sizes, int n_in,
                              void* d_out, int out_size)
{
    const float* x=(const float*)d_in[0];
    const float* conv1_w=(const float*)d_in[1];
    const float* conv1_b=(const float*)d_in[2];
    const float* conv2_w=(const float*)d_in[3];
    const float* conv2_b=(const float*)d_in[4];
    const float* ln1_g=(const float*)d_in[5];
    const float* ln1_b=(const float*)d_in[6];
    const float* wq=(const float*)d_in[7];
    const float* bq=(const float*)d_in[8];
    const float* wk=(const float*)d_in[9];
    const float* bk=(const float*)d_in[10];
    const float* wv=(const float*)d_in[11];
    const float* bv=(const float*)d_in[12];
    const float* wo=(const float*)d_in[13];
    const float* bo=(const float*)d_in[14];
    const float* bias_w=(const float*)d_in[15];
    const float* bias_b=(const float*)d_in[16];
    const float* ln2_g=(const float*)d_in[17];
    const float* ln2_b=(const float*)d_in[18];
    const float* ffn_w1=(const float*)d_in[19];
    const float* ffn_b1=(const float*)d_in[20];
    const float* ffn_w2=(const float*)d_in[21];
    const float* ffn_b2=(const float*)d_in[22];
    const float* fc_w=(const float*)d_in[23];
    const float* fc_b=(const float*)d_in[24];
    float* out=(float*)d_out;

    float *p_cnn,*p_feat,*p_h,*p_hn,*p_attno,*p_ffn,*p_sq,*p_q,*p_k,*p_v,*p_pool;
    cudaGetSymbolAddress((void**)&p_cnn,g_cnn);
    cudaGetSymbolAddress((void**)&p_feat,g_feat);
    cudaGetSymbolAddress((void**)&p_h,g_h);
    cudaGetSymbolAddress((void**)&p_hn,g_hn);
    cudaGetSymbolAddress((void**)&p_attno,g_attno);
    cudaGetSymbolAddress((void**)&p_ffn,g_ffn);
    cudaGetSymbolAddress((void**)&p_sq,g_sq);
    cudaGetSymbolAddress((void**)&p_q,g_q);
    cudaGetSymbolAddress((void**)&p_k,g_k);
    cudaGetSymbolAddress((void**)&p_v,g_v);
    cudaGetSymbolAddress((void**)&p_pool,g_pooled);

    cudaFuncSetAttribute(conv2_mma_kernel,
                         cudaFuncAttributeMaxDynamicSharedMemorySize, CONV2_SMEM_BYTES);
    cudaFuncSetAttribute(attn_kernel,
                         cudaFuncAttributeMaxDynamicSharedMemorySize, ATT_SMEM);
    cudaFuncSetAttribute(gemm_h_kernel,
                         cudaFuncAttributeMaxDynamicSharedMemorySize, GEMM_SMEM);
    cudaFuncSetAttribute(qkv_h_kernel,
                         cudaFuncAttributeMaxDynamicSharedMemorySize, GEMM_SMEM);

    init_kernel<<<1,32>>>();
    conv1_kernel<<<2048,256>>>(x, conv1_w, conv1_b);
    w2p_kernel<<<2048,256>>>(conv2_w);
    conv2_mma_kernel<<<4096,256,CONV2_SMEM_BYTES>>>(conv2_b);
    layernorm_kernel<<<ROWS,256>>>(p_cnn, nullptr, nullptr, p_feat, p_h, p_sq);
    dist_tile_kernel<<<128,256>>>(p_feat);

    dim3 g256(4,32), g512(8,32), gqkv(4,32,3);
    for(int l=0;l<2;l++){
        layernorm_kernel<<<ROWS,256>>>(p_h, ln1_g+l*256, ln1_b+l*256, p_hn, nullptr, nullptr);
        qkv_h_kernel<<<gqkv,256,GEMM_SMEM>>>(p_hn, wq+l*65536, wk+l*65536, wv+l*65536,
                                             bq+l*256, bk+l*256, bv+l*256);
        attn_kernel<<<256,256,ATT_SMEM>>>(p_q, p_k, p_v, bias_w+l*32, bias_b+l*8);
        gemm_h_kernel<<<g256,256,GEMM_SMEM>>>(256,256, p_attno, wo+l*65536, bo+l*256, p_h, p_h, 0);
        layernorm_kernel<<<ROWS,256>>>(p_h, ln2_g+l*256, ln2_b+l*256, p_hn, nullptr, nullptr);
        gemm_h_kernel<<<g512,256,GEMM_SMEM>>>(512,256, p_hn, ffn_w1+l*131072, ffn_b1+l*512, nullptr, p_ffn, 1);
        gemm_h_kernel<<<g256,256,GEMM_SMEM>>>(256,512, p_ffn, ffn_w2+l*131072, ffn_b2+l*256, p_h, p_h, 0);
    }
    pool_kernel<<<64,256>>>(p_pool);
    fc_kernel<<<8,256>>>(p_pool, fc_w, fc_b, out);
}